// round 14
// baseline (speedup 1.0000x reference)
#include <cuda_runtime.h>
#include <cuda_bf16.h>
#include <cstdint>

#define BB 4
#define SS 2048
#define DD 512
#define HH 8
#define HDIM 64
#define MTOT 8192
#define KP 256            // k-pairs per 512-col row
#define NKVSH 2048

// ---------------- device scratch (pair-packed bf16x2 in u32) ----------------
__device__ __align__(16) uint32_t g_A1h[MTOT * KP], g_A1l[MTOT * KP];
__device__ __align__(16) uint32_t g_A2h[MTOT * KP], g_A2l[MTOT * KP];
__device__ __align__(16) uint32_t g_Wh[KP * (DD + NKVSH + DD)];
__device__ __align__(16) uint32_t g_Wl[KP * (DD + NKVSH + DD)];
__device__ __align__(16) uint32_t g_Qh[MTOT * KP], g_Ql[MTOT * KP];
__device__ __align__(16) float    g_KVSH[MTOT * NKVSH];
// fragment-order blobs: [bh][chunk(32)][2048 u32]
__device__ __align__(16) uint32_t g_KBh[32 * 32 * 2048], g_KBl[32 * 32 * 2048];
__device__ __align__(16) uint32_t g_VBh[32 * 32 * 2048], g_VBl[32 * 32 * 2048];
__device__ __align__(16) uint32_t g_Oh[MTOT * KP], g_Ol[MTOT * KP];
__device__ __align__(16) float    g_bKVSH[NKVSH];

#define WOFS_Q 0
#define WOFS_KVSH (KP * DD)
#define WOFS_O (KP * DD + KP * NKVSH)

// ---------------- helpers ----------------
__device__ __forceinline__ void split2(float x0, float x1, uint32_t& hi, uint32_t& lo)
{
    __nv_bfloat16 h0 = __float2bfloat16(x0);
    __nv_bfloat16 h1 = __float2bfloat16(x1);
    __nv_bfloat16 l0 = __float2bfloat16(x0 - __bfloat162float(h0));
    __nv_bfloat16 l1 = __float2bfloat16(x1 - __bfloat162float(h1));
    __nv_bfloat162 H; H.x = h0; H.y = h1;
    __nv_bfloat162 L; L.x = l0; L.y = l1;
    hi = *reinterpret_cast<uint32_t*>(&H);
    lo = *reinterpret_cast<uint32_t*>(&L);
}

__device__ __forceinline__ void mma16816(float c[4],
                                         uint32_t a0, uint32_t a1, uint32_t a2, uint32_t a3,
                                         uint32_t b0, uint32_t b1)
{
    asm volatile(
        "mma.sync.aligned.m16n8k16.row.col.f32.bf16.bf16.f32 "
        "{%0,%1,%2,%3}, {%4,%5,%6,%7}, {%8,%9}, {%0,%1,%2,%3};\n"
        : "+f"(c[0]), "+f"(c[1]), "+f"(c[2]), "+f"(c[3])
        : "r"(a0), "r"(a1), "r"(a2), "r"(a3), "r"(b0), "r"(b1));
}

__device__ __forceinline__ void cpa16(uint32_t* dst_smem, const uint32_t* src)
{
    uint32_t d = (uint32_t)__cvta_generic_to_shared(dst_smem);
    asm volatile("cp.async.cg.shared.global [%0], [%1], 16;\n" :: "r"(d), "l"(src));
}
__device__ __forceinline__ void cpa_commit() { asm volatile("cp.async.commit_group;\n"); }
__device__ __forceinline__ void cpa_wait_all() { asm volatile("cp.async.wait_group 0;\n"); }

// fragment-blob offset: rowp = dp/kp (0..31), col = key/d (0..63)
__device__ __forceinline__ int blob_off(int rowp, int col)
{
    int ks = rowp >> 3, w = rowp & 7;
    int np = col >> 4, r = col & 15;
    return (((ks * 4 + np) * 32) + ((r & 7) * 4 + (w & 3))) * 4
         + ((r >> 3) * 2 + (w >> 2));
}

// ---------------- conversion kernels (merged) ----------------
__global__ __launch_bounds__(256)
void conv_rows_all(const float* __restrict__ X0, const float* __restrict__ X1)
{
    const float* X = blockIdx.y ? X1 : X0;
    uint32_t* Oh = blockIdx.y ? g_A2h : g_A1h;
    uint32_t* Ol = blockIdx.y ? g_A2l : g_A1l;
    int id = blockIdx.x * 256 + threadIdx.x;
    int fb = id * 8;
    float4 a = *(const float4*)&X[fb];
    float4 b = *(const float4*)&X[fb + 4];
    uint32_t h0, l0, h1, l1, h2, l2, h3, l3;
    split2(a.x, a.y, h0, l0);
    split2(a.z, a.w, h1, l1);
    split2(b.x, b.y, h2, l2);
    split2(b.z, b.w, h3, l3);
    int p = id * 4;
    Oh[p] = h0; Oh[p + 1] = h1; Oh[p + 2] = h2; Oh[p + 3] = h3;
    Ol[p] = l0; Ol[p + 1] = l1; Ol[p + 2] = l2; Ol[p + 3] = l3;
}

__global__ __launch_bounds__(256)
void conv_cols_all(const float* __restrict__ W0, const float* __restrict__ W1,
                   const float* __restrict__ W2, const float* __restrict__ W3,
                   const float* __restrict__ W4, const float* __restrict__ W5)
{
    const float* W; int ldo, colofs, base;
    switch (blockIdx.y) {
        case 0:  W = W0; ldo = DD;    colofs = 0;    base = WOFS_Q;    break;
        case 1:  W = W1; ldo = NKVSH; colofs = 0;    base = WOFS_KVSH; break;
        case 2:  W = W2; ldo = NKVSH; colofs = 512;  base = WOFS_KVSH; break;
        case 3:  W = W3; ldo = NKVSH; colofs = 1024; base = WOFS_KVSH; break;
        case 4:  W = W4; ldo = NKVSH; colofs = 1536; base = WOFS_KVSH; break;
        default: W = W5; ldo = DD;    colofs = 0;    base = WOFS_O;    break;
    }
    int id = blockIdx.x * 256 + threadIdx.x;
    int kp = id >> 7;
    int n4 = (id & 127) << 2;
    float4 r0 = *(const float4*)&W[(2 * kp) * DD + n4];
    float4 r1 = *(const float4*)&W[(2 * kp + 1) * DD + n4];
    uint32_t h, l;
    int o = base + kp * ldo + colofs + n4;
    split2(r0.x, r1.x, h, l); g_Wh[o + 0] = h; g_Wl[o + 0] = l;
    split2(r0.y, r1.y, h, l); g_Wh[o + 1] = h; g_Wl[o + 1] = l;
    split2(r0.z, r1.z, h, l); g_Wh[o + 2] = h; g_Wl[o + 2] = l;
    split2(r0.w, r1.w, h, l); g_Wh[o + 3] = h; g_Wl[o + 3] = l;
}

__global__ void bias_pack(const float* bk, const float* bv, const float* bs, const float* bsh)
{
    int i = blockIdx.x * 256 + threadIdx.x;
    float v;
    int sec = i >> 9, j = i & 511;
    if (sec == 0) v = bk[j];
    else if (sec == 1) v = bv[j];
    else if (sec == 2) v = bs[j];
    else v = bsh[j];
    g_bKVSH[i] = v;
}

// ---------------- GEMM: 128 threads, 64x128 tile, 4 blocks/SM --------------
#define GLDA 20
#define GLDB 136

template<int EPI>   // 0: fp32 C, 1: pair store scaled by 1/8 (Q for attention)
__global__ __launch_bounds__(128, 4)
void gemm_pairs(const uint32_t* __restrict__ Ah, const uint32_t* __restrict__ Al,
                const uint32_t* __restrict__ Bh, const uint32_t* __restrict__ Bl,
                int NB, const float* __restrict__ bias,
                float* __restrict__ C, uint32_t* __restrict__ Ch, uint32_t* __restrict__ Cl)
{
    extern __shared__ uint32_t sm[];
    uint32_t* sAh = sm;                    // [2][64*GLDA]
    uint32_t* sAl = sAh + 2 * 64 * GLDA;
    uint32_t* sBh = sAl + 2 * 64 * GLDA;   // [2][16*GLDB]
    uint32_t* sBl = sBh + 2 * 16 * GLDB;

    const int m0 = blockIdx.y * 64;
    const int n0b = blockIdx.x * 128;
    const int tid = threadIdx.x;
    const int warp = tid >> 5;             // 0..3
    const int lane = tid & 31;
    const int g = lane >> 2;
    const int tig = lane & 3;
    const int wn = warp * 32;

    float acc[4][4][4];
#pragma unroll
    for (int mt = 0; mt < 4; ++mt)
#pragma unroll
        for (int nt = 0; nt < 4; ++nt)
#pragma unroll
            for (int r = 0; r < 4; ++r) acc[mt][nt][r] = 0.f;

    auto loadTile = [&](int kt, int buf) {
        int kp0 = kt * 16;
#pragma unroll
        for (int it = 0; it < 2; ++it) {       // A: 64 rows x 16 u32
            int id = it * 128 + tid;
            int r = id >> 2, ch = (id & 3) << 2;
            int so = buf * 64 * GLDA + r * GLDA + ch;
            int go = (m0 + r) * KP + kp0 + ch;
            cpa16(&sAh[so], &Ah[go]);
            cpa16(&sAl[so], &Al[go]);
        }
#pragma unroll
        for (int it = 0; it < 4; ++it) {       // B: 16 kp x 128 u32
            int id = it * 128 + tid;
            int kp = id >> 5, ch = (id & 31) << 2;
            int so = buf * 16 * GLDB + kp * GLDB + ch;
            int go = (kp0 + kp) * NB + n0b + ch;
            cpa16(&sBh[so], &Bh[go]);
            cpa16(&sBl[so], &Bl[go]);
        }
    };

    loadTile(0, 0);
    cpa_commit();

    for (int kt = 0; kt < 16; ++kt) {
        cpa_wait_all();
        __syncthreads();
        if (kt + 1 < 16) { loadTile(kt + 1, (kt + 1) & 1); cpa_commit(); }
        const int buf = kt & 1;
        const int aB = buf * 64 * GLDA;
        const int bB = buf * 16 * GLDB;
#pragma unroll
        for (int s = 0; s < 2; ++s) {
            uint32_t ah[4][4], al[4][4], bh[4][2], bl[4][2];
#pragma unroll
            for (int mt = 0; mt < 4; ++mt) {
                int r0 = aB + (mt * 16 + g) * GLDA + s * 8;
                int r1 = aB + (mt * 16 + g + 8) * GLDA + s * 8;
                ah[mt][0] = sAh[r0 + tig];     ah[mt][1] = sAh[r1 + tig];
                ah[mt][2] = sAh[r0 + tig + 4]; ah[mt][3] = sAh[r1 + tig + 4];
                al[mt][0] = sAl[r0 + tig];     al[mt][1] = sAl[r1 + tig];
                al[mt][2] = sAl[r0 + tig + 4]; al[mt][3] = sAl[r1 + tig + 4];
            }
#pragma unroll
            for (int nt = 0; nt < 4; ++nt) {
                int col = wn + nt * 8 + g;
                int b0 = bB + (s * 8 + tig) * GLDB + col;
                int b1 = bB + (s * 8 + tig + 4) * GLDB + col;
                bh[nt][0] = sBh[b0]; bh[nt][1] = sBh[b1];
                bl[nt][0] = sBl[b0]; bl[nt][1] = sBl[b1];
            }
#pragma unroll
            for (int mt = 0; mt < 4; ++mt)
#pragma unroll
                for (int nt = 0; nt < 4; ++nt)
                    mma16816(acc[mt][nt], ah[mt][0], ah[mt][1], ah[mt][2], ah[mt][3],
                             bh[nt][0], bh[nt][1]);
#pragma unroll
            for (int mt = 0; mt < 4; ++mt)
#pragma unroll
                for (int nt = 0; nt < 4; ++nt)
                    mma16816(acc[mt][nt], ah[mt][0], ah[mt][1], ah[mt][2], ah[mt][3],
                             bl[nt][0], bl[nt][1]);
#pragma unroll
            for (int mt = 0; mt < 4; ++mt)
#pragma unroll
                for (int nt = 0; nt < 4; ++nt)
                    mma16816(acc[mt][nt], al[mt][0], al[mt][1], al[mt][2], al[mt][3],
                             bh[nt][0], bh[nt][1]);
        }
    }

#pragma unroll
    for (int mt = 0; mt < 4; ++mt) {
        int row0 = m0 + mt * 16 + g;
        int row1 = row0 + 8;
#pragma unroll
        for (int nt = 0; nt < 4; ++nt) {
            int col = n0b + wn + nt * 8 + 2 * tig;
            float b0 = bias[col], b1 = bias[col + 1];
            if (EPI == 0) {
                *(float2*)&C[(size_t)row0 * NB + col] =
                    make_float2(acc[mt][nt][0] + b0, acc[mt][nt][1] + b1);
                *(float2*)&C[(size_t)row1 * NB + col] =
                    make_float2(acc[mt][nt][2] + b0, acc[mt][nt][3] + b1);
            } else {
                int dpi = col >> 1;
                uint32_t hh, ll;
                split2((acc[mt][nt][0] + b0) * 0.125f, (acc[mt][nt][1] + b1) * 0.125f, hh, ll);
                Ch[(size_t)row0 * KP + dpi] = hh; Cl[(size_t)row0 * KP + dpi] = ll;
                split2((acc[mt][nt][2] + b0) * 0.125f, (acc[mt][nt][3] + b1) * 0.125f, hh, ll);
                Ch[(size_t)row1 * KP + dpi] = hh; Cl[(size_t)row1 * KP + dpi] = ll;
            }
        }
    }
}

// ---------------- KVSH -> fragment-order K/V blobs (smem-staged) -----------
__global__ __launch_bounds__(256)
void kvss_pack()
{
    __shared__ uint32_t sKh[2048], sKl[2048], sVh[2048], sVl[2048];

    const int h = blockIdx.x;
    const int kb = blockIdx.y;
    const int b = kb >> 5;
    const int cidx = kb & 31;
    const int key0 = cidx * 64;
    const int bh = b * HH + h;
    const int tid = threadIdx.x;
    const int c = (tid & 15) << 2;

#pragma unroll
    for (int it = 0; it < 2; ++it) {
        int kpl = (tid >> 4) + it * 16;
        int r = b * SS + key0 + 2 * kpl;
        const float* base0 = &g_KVSH[(size_t)r * NKVSH];
        const float* base1 = base0 + NKVSH;
        int co = h * 64 + c;
        float4 k0 = *(const float4*)&base0[co];
        float4 k1 = *(const float4*)&base1[co];
        float4 v0 = *(const float4*)&base0[512 + co];
        float4 v1 = *(const float4*)&base1[512 + co];
        float4 s0 = *(const float4*)&base0[1024 + co];
        float4 s1 = *(const float4*)&base1[1024 + co];
        float4 t0 = *(const float4*)&base0[1536 + co];
        float4 t1 = *(const float4*)&base1[1536 + co];

        float K0[4] = {fmaf(k0.x, s0.x, t0.x), fmaf(k0.y, s0.y, t0.y),
                       fmaf(k0.z, s0.z, t0.z), fmaf(k0.w, s0.w, t0.w)};
        float K1[4] = {fmaf(k1.x, s1.x, t1.x), fmaf(k1.y, s1.y, t1.y),
                       fmaf(k1.z, s1.z, t1.z), fmaf(k1.w, s1.w, t1.w)};
        float V0[4] = {fmaf(v0.x, s0.x, t0.x), fmaf(v0.y, s0.y, t0.y),
                       fmaf(v0.z, s0.z, t0.z), fmaf(v0.w, s0.w, t0.w)};
        float V1[4] = {fmaf(v1.x, s1.x, t1.x), fmaf(v1.y, s1.y, t1.y),
                       fmaf(v1.z, s1.z, t1.z), fmaf(v1.w, s1.w, t1.w)};

#pragma unroll
        for (int jj = 0; jj < 4; ++jj) {
            uint32_t hh, ll;
            split2(V0[jj], V1[jj], hh, ll);
            int off = blob_off(kpl, c + jj);
            sVh[off] = hh;
            sVl[off] = ll;
        }
#pragma unroll
        for (int jp = 0; jp < 2; ++jp) {
            int dp = (c >> 1) + jp;
            uint32_t h0_, l0_, h1_, l1_;
            split2(K0[2 * jp], K0[2 * jp + 1], h0_, l0_);
            split2(K1[2 * jp], K1[2 * jp + 1], h1_, l1_);
            int o0 = blob_off(dp, 2 * kpl);
            int o1 = blob_off(dp, 2 * kpl + 1);
            sKh[o0] = h0_; sKl[o0] = l0_;
            sKh[o1] = h1_; sKl[o1] = l1_;
        }
    }
    __syncthreads();

    const size_t blobbase = ((size_t)bh * 32 + cidx) * 2048;
#pragma unroll
    for (int it = 0; it < 2; ++it) {
        int o = (it * 256 + tid) * 4;
        *(uint4*)&g_KBh[blobbase + o] = *(const uint4*)&sKh[o];
        *(uint4*)&g_KBl[blobbase + o] = *(const uint4*)&sKl[o];
        *(uint4*)&g_VBh[blobbase + o] = *(const uint4*)&sVh[o];
        *(uint4*)&g_VBl[blobbase + o] = *(const uint4*)&sVl[o];
    }
}

// ---------------- Flash attention: 128-q tile, 256 thr, register-P ---------
__global__ __launch_bounds__(256, 2)
void attn_pairs()
{
    extern __shared__ uint32_t smA[];
    uint32_t* Kh = smA;                // [2048]
    uint32_t* Kl = Kh + 2048;
    uint32_t* Vh = Kl + 2048;
    uint32_t* Vl = Vh + 2048;

    const int b = blockIdx.z;
    const int h = blockIdx.y;
    const int bh = b * HH + h;
    const int q0 = blockIdx.x * 128;
    const int rowbase = b * SS;
    const int tid = threadIdx.x;
    const int warp = tid >> 5;          // 0..7, each owns 16 q-rows
    const int lane = tid & 31;
    const int g = lane >> 2;
    const int tig = lane & 3;

    const uint32_t* KBh = g_KBh + (size_t)bh * 32 * 2048;
    const uint32_t* KBl = g_KBl + (size_t)bh * 32 * 2048;
    const uint32_t* VBh = g_VBh + (size_t)bh * 32 * 2048;
    const uint32_t* VBl = g_VBl + (size_t)bh * 32 * 2048;

    uint32_t qh[4][4], ql[4][4];
    {
        size_t r0 = (size_t)(rowbase + q0 + warp * 16 + g) * KP + h * 32;
        size_t r1 = r0 + 8 * KP;
#pragma unroll
        for (int s = 0; s < 4; ++s) {
            qh[s][0] = g_Qh[r0 + s * 8 + tig];
            qh[s][1] = g_Qh[r1 + s * 8 + tig];
            qh[s][2] = g_Qh[r0 + s * 8 + tig + 4];
            qh[s][3] = g_Qh[r1 + s * 8 + tig + 4];
            ql[s][0] = g_Ql[r0 + s * 8 + tig];
            ql[s][1] = g_Ql[r1 + s * 8 + tig];
            ql[s][2] = g_Ql[r0 + s * 8 + tig + 4];
            ql[s][3] = g_Ql[r1 + s * 8 + tig + 4];
        }
    }

    auto loadKT = [&](int cidx) {
        const uint32_t* sh = KBh + (size_t)cidx * 2048;
        const uint32_t* sl = KBl + (size_t)cidx * 2048;
#pragma unroll
        for (int it = 0; it < 2; ++it) {
            int o = (it * 256 + tid) * 4;
            cpa16(&Kh[o], &sh[o]);
            cpa16(&Kl[o], &sl[o]);
        }
    };
    auto loadV = [&](int cidx) {
        const uint32_t* sh = VBh + (size_t)cidx * 2048;
        const uint32_t* sl = VBl + (size_t)cidx * 2048;
#pragma unroll
        for (int it = 0; it < 2; ++it) {
            int o = (it * 256 + tid) * 4;
            cpa16(&Vh[o], &sh[o]);
            cpa16(&Vl[o], &sl[o]);
        }
    };

    float o[8][4];
#pragma unroll
    for (int nt = 0; nt < 8; ++nt)
#pragma unroll
        for (int r = 0; r < 4; ++r) o[nt][r] = 0.f;
    float mA = -1e30f, mB = -1e30f, lA = 0.f, lB = 0.f;

    const uint4* K4h = (const uint4*)Kh;
    const uint4* K4l = (const uint4*)Kl;
    const uint4* V4h = (const uint4*)Vh;
    const uint4* V4l = (const uint4*)Vl;

    loadKT(0);
    cpa_commit();

    for (int c = 0; c < 32; ++c) {
        cpa_wait_all();
        __syncthreads();              // KT(c) ready; prev PV readers done
        loadV(c);
        cpa_commit();

        // ---- S = Q @ K^T (scores pre-scaled via Q); vector B loads ----
        float s[8][4];
#pragma unroll
        for (int nt = 0; nt < 8; ++nt)
#pragma unroll
            for (int r = 0; r < 4; ++r) s[nt][r] = 0.f;
#pragma unroll
        for (int ks = 0; ks < 4; ++ks) {
#pragma unroll
            for (int np = 0; np < 4; ++np) {
                const int ntA = np * 2, ntB = ntA + 1;
                uint4 bh4 = K4h[(ks * 4 + np) * 32 + lane];
                uint4 bl4 = K4l[(ks * 4 + np) * 32 + lane];
                mma16816(s[ntA], qh[ks][0], qh[ks][1], qh[ks][2], qh[ks][3], bh4.x, bh4.y);
                mma16816(s[ntB], qh[ks][0], qh[ks][1], qh[ks][2], qh[ks][3], bh4.z, bh4.w);
                mma16816(s[ntA], qh[ks][0], qh[ks][1], qh[ks][2], qh[ks][3], bl4.x, bl4.y);
                mma16816(s[ntB], qh[ks][0], qh[ks][1], qh[ks][2], qh[ks][3], bl4.z, bl4.w);
                mma16816(s[ntA], ql[ks][0], ql[ks][1], ql[ks][2], ql[ks][3], bh4.x, bh4.y);
                mma16816(s[ntB], ql[ks][0], ql[ks][1], ql[ks][2], ql[ks][3], bh4.z, bh4.w);
            }
        }

        // ---- online softmax (rows g / g+8); P packed to registers ----
        float rmA = -1e30f, rmB = -1e30f;
#pragma unroll
        for (int nt = 0; nt < 8; ++nt) {
            rmA = fmaxf(rmA, fmaxf(s[nt][0], s[nt][1]));
            rmB = fmaxf(rmB, fmaxf(s[nt][2], s[nt][3]));
        }
        rmA = fmaxf(rmA, __shfl_xor_sync(0xffffffffu, rmA, 1));
        rmA = fmaxf(rmA, __shfl_xor_sync(0xffffffffu, rmA, 2));
        rmB = fmaxf(rmB, __shfl_xor_sync(0xffffffffu, rmB, 1));
        rmB = fmaxf(rmB, __shfl_xor_sync(0xffffffffu, rmB, 2));

        float mnA = fmaxf(mA, rmA);
        float mnB = fmaxf(mB, rmB);
        float alA = __expf(mA - mnA);
        float alB = __expf(mB - mnB);
        mA = mnA; mB = mnB;

        uint32_t ph[16], pl[16];
        float sumA = 0.f, sumB = 0.f;
#pragma unroll
        for (int nt = 0; nt < 8; ++nt) {
            float p0 = __expf(s[nt][0] - mA);
            float p1 = __expf(s[nt][1] - mA);
            float p2 = __expf(s[nt][2] - mB);
            float p3 = __expf(s[nt][3] - mB);
            sumA += p0 + p1;
            sumB += p2 + p3;
            split2(p0, p1, ph[2 * nt],     pl[2 * nt]);
            split2(p2, p3, ph[2 * nt + 1], pl[2 * nt + 1]);
        }
        sumA += __shfl_xor_sync(0xffffffffu, sumA, 1);
        sumA += __shfl_xor_sync(0xffffffffu, sumA, 2);
        sumB += __shfl_xor_sync(0xffffffffu, sumB, 1);
        sumB += __shfl_xor_sync(0xffffffffu, sumB, 2);
        lA = lA * alA + sumA;
        lB = lB * alB + sumB;
#pragma unroll
        for (int nt = 0; nt < 8; ++nt) {
            o[nt][0] *= alA; o[nt][1] *= alA;
            o[nt][2] *= alB; o[nt][3] *= alB;
        }

        cpa_wait_all();
        __syncthreads();              // V(c) ready; S-mma done with KT
        if (c + 1 < 32) { loadKT(c + 1); cpa_commit(); }

        // ---- O += P @ V; P A-fragments straight from registers ----
#pragma unroll
        for (int ks = 0; ks < 4; ++ks) {
            const uint32_t a0h = ph[4 * ks],     a1h = ph[4 * ks + 1];
            const uint32_t a2h = ph[4 * ks + 2], a3h = ph[4 * ks + 3];
            const uint32_t a0l = pl[4 * ks],     a1l = pl[4 * ks + 1];
            const uint32_t a2l = pl[4 * ks + 2], a3l = pl[4 * ks + 3];
#pragma unroll
            for (int np = 0; np < 4; ++np) {
                const int ntA = np * 2, ntB = ntA + 1;
                uint4 bh4 = V4h[(ks * 4 + np) * 32 + lane];
                uint4 bl4 = V4l[(ks * 4 + np) * 32 + lane];
                mma16816(o[ntA], a0h, a1h, a2h, a3h, bh4.x, bh4.y);
                mma16816(o[ntB], a0h, a1h, a2h, a3h, bh4.z, bh4.w);
                mma16816(o[ntA], a0h, a1h, a2h, a3h, bl4.x, bl4.y);
                mma16816(o[ntB], a0h, a1h, a2h, a3h, bl4.z, bl4.w);
                mma16816(o[ntA], a0l, a1l, a2l, a3l, bh4.x, bh4.y);
                mma16816(o[ntB], a0l, a1l, a2l, a3l, bh4.z, bh4.w);
            }
        }
    }

    // normalize + store as pairs (input layout for O-projection gemm)
    float invA = 1.f / lA;
    float invB = 1.f / lB;
    size_t r0 = (size_t)(rowbase + q0 + warp * 16 + g) * KP + h * 32;
    size_t r1 = r0 + 8 * KP;
#pragma unroll
    for (int nt = 0; nt < 8; ++nt) {
        int dpi = nt * 4 + tig;
        uint32_t hh, ll;
        split2(o[nt][0] * invA, o[nt][1] * invA, hh, ll);
        g_Oh[r0 + dpi] = hh; g_Ol[r0 + dpi] = ll;
        split2(o[nt][2] * invB, o[nt][3] * invB, hh, ll);
        g_Oh[r1 + dpi] = hh; g_Ol[r1 + dpi] = ll;
    }
}

// ---------------------------------------------------------------------------
extern "C" void kernel_launch(void* const* d_in, const int* in_sizes, int n_in,
                              void* d_out, int out_size)
{
    (void)in_sizes; (void)n_in; (void)out_size;

    const float* mod1 = (const float*)d_in[0];
    const float* mod2 = (const float*)d_in[1];
    const float* Wq  = (const float*)d_in[2];  const float* bq  = (const float*)d_in[3];
    const float* Wk  = (const float*)d_in[4];  const float* bk  = (const float*)d_in[5];
    const float* Wv  = (const float*)d_in[6];  const float* bv  = (const float*)d_in[7];
    const float* Wo  = (const float*)d_in[8];  const float* bo  = (const float*)d_in[9];
    const float* Ws  = (const float*)d_in[10]; const float* bs  = (const float*)d_in[11];
    const float* Wsh = (const float*)d_in[12]; const float* bsh = (const float*)d_in[13];
    float* out = (float*)d_out;

    uint32_t *pA1h, *pA1l, *pA2h, *pA2l, *pWh, *pWl, *pQh, *pQl, *pOh, *pOl;
    float *pKVSH, *pbK;
    cudaGetSymbolAddress((void**)&pA1h, g_A1h);
    cudaGetSymbolAddress((void**)&pA1l, g_A1l);
    cudaGetSymbolAddress((void**)&pA2h, g_A2h);
    cudaGetSymbolAddress((void**)&pA2l, g_A2l);
    cudaGetSymbolAddress((void**)&pWh, g_Wh);
    cudaGetSymbolAddress((void**)&pWl, g_Wl);
    cudaGetSymbolAddress((void**)&pQh, g_Qh);
    cudaGetSymbolAddress((void**)&pQl, g_Ql);
    cudaGetSymbolAddress((void**)&pOh, g_Oh);
    cudaGetSymbolAddress((void**)&pOl, g_Ol);
    cudaGetSymbolAddress((void**)&pKVSH, g_KVSH);
    cudaGetSymbolAddress((void**)&pbK, g_bKVSH);

    const int GEMM_SMEM = (2 * 64 * GLDA * 2 + 2 * 16 * GLDB * 2) * 4;   // 55296 B
    const int ATTN_SMEM = 4 * 2048 * 4;                                  // 32768 B
    cudaFuncSetAttribute(gemm_pairs<0>, cudaFuncAttributeMaxDynamicSharedMemorySize, GEMM_SMEM);
    cudaFuncSetAttribute(gemm_pairs<1>, cudaFuncAttributeMaxDynamicSharedMemorySize, GEMM_SMEM);
    cudaFuncSetAttribute(attn_pairs, cudaFuncAttributeMaxDynamicSharedMemorySize, ATTN_SMEM);

    // 1) conversions (3 launches)
    conv_rows_all<<<dim3(MTOT * KP / 4 / 256, 2), 256>>>(mod1, mod2);
    conv_cols_all<<<dim3(128, 6), 256>>>(Wq, Wk, Wv, Ws, Wsh, Wo);
    bias_pack<<<8, 256>>>(bk, bv, bs, bsh);

    // 2) Q projection (pair output, pre-scaled by 1/8)
    gemm_pairs<1><<<dim3(DD / 128, MTOT / 64), 128, GEMM_SMEM>>>(
        pA1h, pA1l, pWh + WOFS_Q, pWl + WOFS_Q, DD, bq, nullptr, pQh, pQl);

    // 3) merged K|V|S|H projection (fp32 output)
    gemm_pairs<0><<<dim3(NKVSH / 128, MTOT / 64), 128, GEMM_SMEM>>>(
        pA2h, pA2l, pWh + WOFS_KVSH, pWl + WOFS_KVSH, NKVSH, pbK, pKVSH, nullptr, nullptr);

    // 4) apply scale/shift + pack fragment-order K/V blobs (smem-staged)
    kvss_pack<<<dim3(HH, 128), 256>>>();

    // 5) attention (128-q tiles, 256 threads, register-P, vector B loads)
    attn_pairs<<<dim3(SS / 128, HH, BB), 256, ATTN_SMEM>>>();

    // 6) output projection
    gemm_pairs<0><<<dim3(DD / 128, MTOT / 64), 128, GEMM_SMEM>>>(
        pOh, pOl, pWh + WOFS_O, pWl + WOFS_O, DD, bo, out, nullptr, nullptr);
}

// round 15
// speedup vs baseline: 1.0940x; 1.0940x over previous
#include <cuda_runtime.h>
#include <cuda_bf16.h>
#include <cstdint>

#define BB 4
#define SS 2048
#define DD 512
#define HH 8
#define HDIM 64
#define MTOT 8192
#define KP 256            // k-pairs per 512-col row
#define NKVSH 2048

// ---------------- device scratch (pair-packed bf16x2 in u32) ----------------
__device__ __align__(16) uint32_t g_A1h[MTOT * KP], g_A1l[MTOT * KP];
__device__ __align__(16) uint32_t g_A2h[MTOT * KP], g_A2l[MTOT * KP];
__device__ __align__(16) uint32_t g_Wh[KP * (DD + NKVSH + DD)];
__device__ __align__(16) uint32_t g_Wl[KP * (DD + NKVSH + DD)];
__device__ __align__(16) uint32_t g_Qh[MTOT * KP], g_Ql[MTOT * KP];
__device__ __align__(16) float    g_KVSH[MTOT * NKVSH];
// fragment-order blobs: [bh][chunk(32)][2048 u32]
__device__ __align__(16) uint32_t g_KBh[32 * 32 * 2048], g_KBl[32 * 32 * 2048];
__device__ __align__(16) uint32_t g_VBh[32 * 32 * 2048], g_VBl[32 * 32 * 2048];
__device__ __align__(16) uint32_t g_Oh[MTOT * KP], g_Ol[MTOT * KP];
__device__ __align__(16) float    g_bKVSH[NKVSH];

#define WOFS_Q 0
#define WOFS_KVSH (KP * DD)
#define WOFS_O (KP * DD + KP * NKVSH)

// ---------------- helpers ----------------
__device__ __forceinline__ void split2(float x0, float x1, uint32_t& hi, uint32_t& lo)
{
    __nv_bfloat16 h0 = __float2bfloat16(x0);
    __nv_bfloat16 h1 = __float2bfloat16(x1);
    __nv_bfloat16 l0 = __float2bfloat16(x0 - __bfloat162float(h0));
    __nv_bfloat16 l1 = __float2bfloat16(x1 - __bfloat162float(h1));
    __nv_bfloat162 H; H.x = h0; H.y = h1;
    __nv_bfloat162 L; L.x = l0; L.y = l1;
    hi = *reinterpret_cast<uint32_t*>(&H);
    lo = *reinterpret_cast<uint32_t*>(&L);
}

__device__ __forceinline__ void mma16816(float c[4],
                                         uint32_t a0, uint32_t a1, uint32_t a2, uint32_t a3,
                                         uint32_t b0, uint32_t b1)
{
    asm volatile(
        "mma.sync.aligned.m16n8k16.row.col.f32.bf16.bf16.f32 "
        "{%0,%1,%2,%3}, {%4,%5,%6,%7}, {%8,%9}, {%0,%1,%2,%3};\n"
        : "+f"(c[0]), "+f"(c[1]), "+f"(c[2]), "+f"(c[3])
        : "r"(a0), "r"(a1), "r"(a2), "r"(a3), "r"(b0), "r"(b1));
}

__device__ __forceinline__ void cpa16(uint32_t* dst_smem, const uint32_t* src)
{
    uint32_t d = (uint32_t)__cvta_generic_to_shared(dst_smem);
    asm volatile("cp.async.cg.shared.global [%0], [%1], 16;\n" :: "r"(d), "l"(src));
}
__device__ __forceinline__ void cpa_commit() { asm volatile("cp.async.commit_group;\n"); }
__device__ __forceinline__ void cpa_wait_all() { asm volatile("cp.async.wait_group 0;\n"); }

// fragment-blob offset: rowp = dp/kp (0..31), col = key/d (0..63)
__device__ __forceinline__ int blob_off(int rowp, int col)
{
    int ks = rowp >> 3, w = rowp & 7;
    int np = col >> 4, r = col & 15;
    return (((ks * 4 + np) * 32) + ((r & 7) * 4 + (w & 3))) * 4
         + ((r >> 3) * 2 + (w >> 2));
}

// ---------------- conversion kernels (merged, uint4 stores) ----------------
__global__ __launch_bounds__(256)
void conv_rows_all(const float* __restrict__ X0, const float* __restrict__ X1)
{
    const float* X = blockIdx.y ? X1 : X0;
    uint32_t* Oh = blockIdx.y ? g_A2h : g_A1h;
    uint32_t* Ol = blockIdx.y ? g_A2l : g_A1l;
    int id = blockIdx.x * 256 + threadIdx.x;
    int fb = id * 8;
    float4 a = *(const float4*)&X[fb];
    float4 b = *(const float4*)&X[fb + 4];
    uint32_t h0, l0, h1, l1, h2, l2, h3, l3;
    split2(a.x, a.y, h0, l0);
    split2(a.z, a.w, h1, l1);
    split2(b.x, b.y, h2, l2);
    split2(b.z, b.w, h3, l3);
    int p = id * 4;
    *(uint4*)&Oh[p] = make_uint4(h0, h1, h2, h3);
    *(uint4*)&Ol[p] = make_uint4(l0, l1, l2, l3);
}

__global__ __launch_bounds__(256)
void conv_cols_all(const float* __restrict__ W0, const float* __restrict__ W1,
                   const float* __restrict__ W2, const float* __restrict__ W3,
                   const float* __restrict__ W4, const float* __restrict__ W5)
{
    const float* W; int ldo, colofs, base;
    switch (blockIdx.y) {
        case 0:  W = W0; ldo = DD;    colofs = 0;    base = WOFS_Q;    break;
        case 1:  W = W1; ldo = NKVSH; colofs = 0;    base = WOFS_KVSH; break;
        case 2:  W = W2; ldo = NKVSH; colofs = 512;  base = WOFS_KVSH; break;
        case 3:  W = W3; ldo = NKVSH; colofs = 1024; base = WOFS_KVSH; break;
        case 4:  W = W4; ldo = NKVSH; colofs = 1536; base = WOFS_KVSH; break;
        default: W = W5; ldo = DD;    colofs = 0;    base = WOFS_O;    break;
    }
    int id = blockIdx.x * 256 + threadIdx.x;
    int kp = id >> 7;
    int n4 = (id & 127) << 2;
    float4 r0 = *(const float4*)&W[(2 * kp) * DD + n4];
    float4 r1 = *(const float4*)&W[(2 * kp + 1) * DD + n4];
    uint32_t h0, l0, h1, l1, h2, l2, h3, l3;
    split2(r0.x, r1.x, h0, l0);
    split2(r0.y, r1.y, h1, l1);
    split2(r0.z, r1.z, h2, l2);
    split2(r0.w, r1.w, h3, l3);
    int o = base + kp * ldo + colofs + n4;
    *(uint4*)&g_Wh[o] = make_uint4(h0, h1, h2, h3);
    *(uint4*)&g_Wl[o] = make_uint4(l0, l1, l2, l3);
}

__global__ void bias_pack(const float* bk, const float* bv, const float* bs, const float* bsh)
{
    int i = blockIdx.x * 256 + threadIdx.x;
    float v;
    int sec = i >> 9, j = i & 511;
    if (sec == 0) v = bk[j];
    else if (sec == 1) v = bv[j];
    else if (sec == 2) v = bs[j];
    else v = bsh[j];
    g_bKVSH[i] = v;
}

// ---------------- GEMM core: 128 threads, 64x128 tile ----------------------
#define GLDA 20
#define GLDB 136

__device__ __forceinline__ void gemm_core(
    const uint32_t* __restrict__ Ah, const uint32_t* __restrict__ Al,
    const uint32_t* __restrict__ Bh, const uint32_t* __restrict__ Bl,
    int NB, int m0, int n0b, uint32_t* sm, float acc[4][4][4])
{
    uint32_t* sAh = sm;                    // [2][64*GLDA]
    uint32_t* sAl = sAh + 2 * 64 * GLDA;
    uint32_t* sBh = sAl + 2 * 64 * GLDA;   // [2][16*GLDB]
    uint32_t* sBl = sBh + 2 * 16 * GLDB;

    const int tid = threadIdx.x;
    const int warp = tid >> 5;
    const int lane = tid & 31;
    const int g = lane >> 2;
    const int tig = lane & 3;
    const int wn = warp * 32;

    auto loadTile = [&](int kt, int buf) {
        int kp0 = kt * 16;
#pragma unroll
        for (int it = 0; it < 2; ++it) {       // A: 64 rows x 16 u32
            int id = it * 128 + tid;
            int r = id >> 2, ch = (id & 3) << 2;
            int so = buf * 64 * GLDA + r * GLDA + ch;
            int go = (m0 + r) * KP + kp0 + ch;
            cpa16(&sAh[so], &Ah[go]);
            cpa16(&sAl[so], &Al[go]);
        }
#pragma unroll
        for (int it = 0; it < 4; ++it) {       // B: 16 kp x 128 u32
            int id = it * 128 + tid;
            int kp = id >> 5, ch = (id & 31) << 2;
            int so = buf * 16 * GLDB + kp * GLDB + ch;
            int go = (kp0 + kp) * NB + n0b + ch;
            cpa16(&sBh[so], &Bh[go]);
            cpa16(&sBl[so], &Bl[go]);
        }
    };

    loadTile(0, 0);
    cpa_commit();

    for (int kt = 0; kt < 16; ++kt) {
        cpa_wait_all();
        __syncthreads();
        if (kt + 1 < 16) { loadTile(kt + 1, (kt + 1) & 1); cpa_commit(); }
        const int buf = kt & 1;
        const int aB = buf * 64 * GLDA;
        const int bB = buf * 16 * GLDB;
#pragma unroll
        for (int s = 0; s < 2; ++s) {
            uint32_t ah[4][4], al[4][4], bh[4][2], bl[4][2];
#pragma unroll
            for (int mt = 0; mt < 4; ++mt) {
                int r0 = aB + (mt * 16 + g) * GLDA + s * 8;
                int r1 = aB + (mt * 16 + g + 8) * GLDA + s * 8;
                ah[mt][0] = sAh[r0 + tig];     ah[mt][1] = sAh[r1 + tig];
                ah[mt][2] = sAh[r0 + tig + 4]; ah[mt][3] = sAh[r1 + tig + 4];
                al[mt][0] = sAl[r0 + tig];     al[mt][1] = sAl[r1 + tig];
                al[mt][2] = sAl[r0 + tig + 4]; al[mt][3] = sAl[r1 + tig + 4];
            }
#pragma unroll
            for (int nt = 0; nt < 4; ++nt) {
                int col = wn + nt * 8 + g;
                int b0 = bB + (s * 8 + tig) * GLDB + col;
                int b1 = bB + (s * 8 + tig + 4) * GLDB + col;
                bh[nt][0] = sBh[b0]; bh[nt][1] = sBh[b1];
                bl[nt][0] = sBl[b0]; bl[nt][1] = sBl[b1];
            }
#pragma unroll
            for (int mt = 0; mt < 4; ++mt)
#pragma unroll
                for (int nt = 0; nt < 4; ++nt)
                    mma16816(acc[mt][nt], ah[mt][0], ah[mt][1], ah[mt][2], ah[mt][3],
                             bh[nt][0], bh[nt][1]);
#pragma unroll
            for (int mt = 0; mt < 4; ++mt)
#pragma unroll
                for (int nt = 0; nt < 4; ++nt)
                    mma16816(acc[mt][nt], ah[mt][0], ah[mt][1], ah[mt][2], ah[mt][3],
                             bl[nt][0], bl[nt][1]);
#pragma unroll
            for (int mt = 0; mt < 4; ++mt)
#pragma unroll
                for (int nt = 0; nt < 4; ++nt)
                    mma16816(acc[mt][nt], al[mt][0], al[mt][1], al[mt][2], al[mt][3],
                             bh[nt][0], bh[nt][1]);
        }
    }
}

// ---- merged Q + KVSH projection: grid (20, 128) ----
__global__ __launch_bounds__(128, 4)
void gemm_qkvsh(const float* __restrict__ bq)
{
    extern __shared__ uint32_t sm[];
    const bool qmode = blockIdx.x < 4;
    const int m0 = blockIdx.y * 64;
    const int n0b = qmode ? blockIdx.x * 128 : (blockIdx.x - 4) * 128;
    const int NB = qmode ? DD : NKVSH;
    const uint32_t* Ah = qmode ? g_A1h : g_A2h;
    const uint32_t* Al = qmode ? g_A1l : g_A2l;
    const uint32_t* Bh = g_Wh + (qmode ? WOFS_Q : WOFS_KVSH);
    const uint32_t* Bl = g_Wl + (qmode ? WOFS_Q : WOFS_KVSH);

    float acc[4][4][4];
#pragma unroll
    for (int mt = 0; mt < 4; ++mt)
#pragma unroll
        for (int nt = 0; nt < 4; ++nt)
#pragma unroll
            for (int r = 0; r < 4; ++r) acc[mt][nt][r] = 0.f;

    gemm_core(Ah, Al, Bh, Bl, NB, m0, n0b, sm, acc);

    const int tid = threadIdx.x;
    const int warp = tid >> 5;
    const int lane = tid & 31;
    const int g = lane >> 2;
    const int tig = lane & 3;
    const int wn = warp * 32;

#pragma unroll
    for (int mt = 0; mt < 4; ++mt) {
        int row0 = m0 + mt * 16 + g;
        int row1 = row0 + 8;
#pragma unroll
        for (int nt = 0; nt < 4; ++nt) {
            int col = n0b + wn + nt * 8 + 2 * tig;
            if (qmode) {
                float b0 = bq[col], b1 = bq[col + 1];
                int dpi = col >> 1;
                uint32_t hh, ll;
                split2((acc[mt][nt][0] + b0) * 0.125f, (acc[mt][nt][1] + b1) * 0.125f, hh, ll);
                g_Qh[(size_t)row0 * KP + dpi] = hh; g_Ql[(size_t)row0 * KP + dpi] = ll;
                split2((acc[mt][nt][2] + b0) * 0.125f, (acc[mt][nt][3] + b1) * 0.125f, hh, ll);
                g_Qh[(size_t)row1 * KP + dpi] = hh; g_Ql[(size_t)row1 * KP + dpi] = ll;
            } else {
                float b0 = g_bKVSH[col], b1 = g_bKVSH[col + 1];
                *(float2*)&g_KVSH[(size_t)row0 * NKVSH + col] =
                    make_float2(acc[mt][nt][0] + b0, acc[mt][nt][1] + b1);
                *(float2*)&g_KVSH[(size_t)row1 * NKVSH + col] =
                    make_float2(acc[mt][nt][2] + b0, acc[mt][nt][3] + b1);
            }
        }
    }
}

// ---- O projection ----
__global__ __launch_bounds__(128, 4)
void gemm_oproj(const float* __restrict__ bias, float* __restrict__ C)
{
    extern __shared__ uint32_t sm[];
    const int m0 = blockIdx.y * 64;
    const int n0b = blockIdx.x * 128;

    float acc[4][4][4];
#pragma unroll
    for (int mt = 0; mt < 4; ++mt)
#pragma unroll
        for (int nt = 0; nt < 4; ++nt)
#pragma unroll
            for (int r = 0; r < 4; ++r) acc[mt][nt][r] = 0.f;

    gemm_core(g_Oh, g_Ol, g_Wh + WOFS_O, g_Wl + WOFS_O, DD, m0, n0b, sm, acc);

    const int tid = threadIdx.x;
    const int warp = tid >> 5;
    const int lane = tid & 31;
    const int g = lane >> 2;
    const int tig = lane & 3;
    const int wn = warp * 32;

#pragma unroll
    for (int mt = 0; mt < 4; ++mt) {
        int row0 = m0 + mt * 16 + g;
        int row1 = row0 + 8;
#pragma unroll
        for (int nt = 0; nt < 4; ++nt) {
            int col = n0b + wn + nt * 8 + 2 * tig;
            float b0 = bias[col], b1 = bias[col + 1];
            *(float2*)&C[(size_t)row0 * DD + col] =
                make_float2(acc[mt][nt][0] + b0, acc[mt][nt][1] + b1);
            *(float2*)&C[(size_t)row1 * DD + col] =
                make_float2(acc[mt][nt][2] + b0, acc[mt][nt][3] + b1);
        }
    }
}

// ---------------- KVSH -> fragment-order K/V blobs (smem-staged) -----------
__global__ __launch_bounds__(256)
void kvss_pack()
{
    __shared__ uint32_t sKh[2048], sKl[2048], sVh[2048], sVl[2048];

    const int h = blockIdx.x;
    const int kb = blockIdx.y;
    const int b = kb >> 5;
    const int cidx = kb & 31;
    const int key0 = cidx * 64;
    const int bh = b * HH + h;
    const int tid = threadIdx.x;
    const int c = (tid & 15) << 2;

#pragma unroll
    for (int it = 0; it < 2; ++it) {
        int kpl = (tid >> 4) + it * 16;
        int r = b * SS + key0 + 2 * kpl;
        const float* base0 = &g_KVSH[(size_t)r * NKVSH];
        const float* base1 = base0 + NKVSH;
        int co = h * 64 + c;
        float4 k0 = *(const float4*)&base0[co];
        float4 k1 = *(const float4*)&base1[co];
        float4 v0 = *(const float4*)&base0[512 + co];
        float4 v1 = *(const float4*)&base1[512 + co];
        float4 s0 = *(const float4*)&base0[1024 + co];
        float4 s1 = *(const float4*)&base1[1024 + co];
        float4 t0 = *(const float4*)&base0[1536 + co];
        float4 t1 = *(const float4*)&base1[1536 + co];

        float K0[4] = {fmaf(k0.x, s0.x, t0.x), fmaf(k0.y, s0.y, t0.y),
                       fmaf(k0.z, s0.z, t0.z), fmaf(k0.w, s0.w, t0.w)};
        float K1[4] = {fmaf(k1.x, s1.x, t1.x), fmaf(k1.y, s1.y, t1.y),
                       fmaf(k1.z, s1.z, t1.z), fmaf(k1.w, s1.w, t1.w)};
        float V0[4] = {fmaf(v0.x, s0.x, t0.x), fmaf(v0.y, s0.y, t0.y),
                       fmaf(v0.z, s0.z, t0.z), fmaf(v0.w, s0.w, t0.w)};
        float V1[4] = {fmaf(v1.x, s1.x, t1.x), fmaf(v1.y, s1.y, t1.y),
                       fmaf(v1.z, s1.z, t1.z), fmaf(v1.w, s1.w, t1.w)};

#pragma unroll
        for (int jj = 0; jj < 4; ++jj) {
            uint32_t hh, ll;
            split2(V0[jj], V1[jj], hh, ll);
            int off = blob_off(kpl, c + jj);
            sVh[off] = hh;
            sVl[off] = ll;
        }
#pragma unroll
        for (int jp = 0; jp < 2; ++jp) {
            int dp = (c >> 1) + jp;
            uint32_t h0_, l0_, h1_, l1_;
            split2(K0[2 * jp], K0[2 * jp + 1], h0_, l0_);
            split2(K1[2 * jp], K1[2 * jp + 1], h1_, l1_);
            int o0 = blob_off(dp, 2 * kpl);
            int o1 = blob_off(dp, 2 * kpl + 1);
            sKh[o0] = h0_; sKl[o0] = l0_;
            sKh[o1] = h1_; sKl[o1] = l1_;
        }
    }
    __syncthreads();

    const size_t blobbase = ((size_t)bh * 32 + cidx) * 2048;
#pragma unroll
    for (int it = 0; it < 2; ++it) {
        int o = (it * 256 + tid) * 4;
        *(uint4*)&g_KBh[blobbase + o] = *(const uint4*)&sKh[o];
        *(uint4*)&g_KBl[blobbase + o] = *(const uint4*)&sKl[o];
        *(uint4*)&g_VBh[blobbase + o] = *(const uint4*)&sVh[o];
        *(uint4*)&g_VBl[blobbase + o] = *(const uint4*)&sVl[o];
    }
}

// ---------------- Flash attention: 64-q, 128 thr, register-P (R13) ---------
__global__ __launch_bounds__(128, 4)
void attn_pairs()
{
    extern __shared__ uint32_t smA[];
    uint32_t* Kh = smA;                // [2048]
    uint32_t* Kl = Kh + 2048;
    uint32_t* Vh = Kl + 2048;
    uint32_t* Vl = Vh + 2048;

    const int b = blockIdx.z;
    const int h = blockIdx.y;
    const int bh = b * HH + h;
    const int q0 = blockIdx.x * 64;
    const int rowbase = b * SS;
    const int tid = threadIdx.x;
    const int warp = tid >> 5;
    const int lane = tid & 31;
    const int g = lane >> 2;
    const int tig = lane & 3;

    const uint32_t* KBh = g_KBh + (size_t)bh * 32 * 2048;
    const uint32_t* KBl = g_KBl + (size_t)bh * 32 * 2048;
    const uint32_t* VBh = g_VBh + (size_t)bh * 32 * 2048;
    const uint32_t* VBl = g_VBl + (size_t)bh * 32 * 2048;

    uint32_t qh[4][4], ql[4][4];
    {
        size_t r0 = (size_t)(rowbase + q0 + warp * 16 + g) * KP + h * 32;
        size_t r1 = r0 + 8 * KP;
#pragma unroll
        for (int s = 0; s < 4; ++s) {
            qh[s][0] = g_Qh[r0 + s * 8 + tig];
            qh[s][1] = g_Qh[r1 + s * 8 + tig];
            qh[s][2] = g_Qh[r0 + s * 8 + tig + 4];
            qh[s][3] = g_Qh[r1 + s * 8 + tig + 4];
            ql[s][0] = g_Ql[r0 + s * 8 + tig];
            ql[s][1] = g_Ql[r1 + s * 8 + tig];
            ql[s][2] = g_Ql[r0 + s * 8 + tig + 4];
            ql[s][3] = g_Ql[r1 + s * 8 + tig + 4];
        }
    }

    auto loadKT = [&](int cidx) {
        const uint32_t* sh = KBh + (size_t)cidx * 2048;
        const uint32_t* sl = KBl + (size_t)cidx * 2048;
#pragma unroll
        for (int it = 0; it < 4; ++it) {
            int o = (it * 128 + tid) * 4;
            cpa16(&Kh[o], &sh[o]);
            cpa16(&Kl[o], &sl[o]);
        }
    };
    auto loadV = [&](int cidx) {
        const uint32_t* sh = VBh + (size_t)cidx * 2048;
        const uint32_t* sl = VBl + (size_t)cidx * 2048;
#pragma unroll
        for (int it = 0; it < 4; ++it) {
            int o = (it * 128 + tid) * 4;
            cpa16(&Vh[o], &sh[o]);
            cpa16(&Vl[o], &sl[o]);
        }
    };

    float o[8][4];
#pragma unroll
    for (int nt = 0; nt < 8; ++nt)
#pragma unroll
        for (int r = 0; r < 4; ++r) o[nt][r] = 0.f;
    float mA = -1e30f, mB = -1e30f, lA = 0.f, lB = 0.f;

    const uint4* K4h = (const uint4*)Kh;
    const uint4* K4l = (const uint4*)Kl;
    const uint4* V4h = (const uint4*)Vh;
    const uint4* V4l = (const uint4*)Vl;

    loadKT(0);
    cpa_commit();

    for (int c = 0; c < 32; ++c) {
        cpa_wait_all();
        __syncthreads();              // KT(c) ready; prev PV readers done
        loadV(c);
        cpa_commit();

        // ---- S = Q @ K^T (scores pre-scaled via Q); vector B loads ----
        float s[8][4];
#pragma unroll
        for (int nt = 0; nt < 8; ++nt)
#pragma unroll
            for (int r = 0; r < 4; ++r) s[nt][r] = 0.f;
#pragma unroll
        for (int ks = 0; ks < 4; ++ks) {
#pragma unroll
            for (int np = 0; np < 4; ++np) {
                const int ntA = np * 2, ntB = ntA + 1;
                uint4 bh4 = K4h[(ks * 4 + np) * 32 + lane];
                uint4 bl4 = K4l[(ks * 4 + np) * 32 + lane];
                mma16816(s[ntA], qh[ks][0], qh[ks][1], qh[ks][2], qh[ks][3], bh4.x, bh4.y);
                mma16816(s[ntB], qh[ks][0], qh[ks][1], qh[ks][2], qh[ks][3], bh4.z, bh4.w);
                mma16816(s[ntA], qh[ks][0], qh[ks][1], qh[ks][2], qh[ks][3], bl4.x, bl4.y);
                mma16816(s[ntB], qh[ks][0], qh[ks][1], qh[ks][2], qh[ks][3], bl4.z, bl4.w);
                mma16816(s[ntA], ql[ks][0], ql[ks][1], ql[ks][2], ql[ks][3], bh4.x, bh4.y);
                mma16816(s[ntB], ql[ks][0], ql[ks][1], ql[ks][2], ql[ks][3], bh4.z, bh4.w);
            }
        }

        // ---- online softmax (rows g / g+8); P packed to registers ----
        float rmA = -1e30f, rmB = -1e30f;
#pragma unroll
        for (int nt = 0; nt < 8; ++nt) {
            rmA = fmaxf(rmA, fmaxf(s[nt][0], s[nt][1]));
            rmB = fmaxf(rmB, fmaxf(s[nt][2], s[nt][3]));
        }
        rmA = fmaxf(rmA, __shfl_xor_sync(0xffffffffu, rmA, 1));
        rmA = fmaxf(rmA, __shfl_xor_sync(0xffffffffu, rmA, 2));
        rmB = fmaxf(rmB, __shfl_xor_sync(0xffffffffu, rmB, 1));
        rmB = fmaxf(rmB, __shfl_xor_sync(0xffffffffu, rmB, 2));

        float mnA = fmaxf(mA, rmA);
        float mnB = fmaxf(mB, rmB);
        float alA = __expf(mA - mnA);
        float alB = __expf(mB - mnB);
        mA = mnA; mB = mnB;

        uint32_t ph[16], pl[16];
        float sumA = 0.f, sumB = 0.f;
#pragma unroll
        for (int nt = 0; nt < 8; ++nt) {
            float p0 = __expf(s[nt][0] - mA);
            float p1 = __expf(s[nt][1] - mA);
            float p2 = __expf(s[nt][2] - mB);
            float p3 = __expf(s[nt][3] - mB);
            sumA += p0 + p1;
            sumB += p2 + p3;
            split2(p0, p1, ph[2 * nt],     pl[2 * nt]);
            split2(p2, p3, ph[2 * nt + 1], pl[2 * nt + 1]);
        }
        sumA += __shfl_xor_sync(0xffffffffu, sumA, 1);
        sumA += __shfl_xor_sync(0xffffffffu, sumA, 2);
        sumB += __shfl_xor_sync(0xffffffffu, sumB, 1);
        sumB += __shfl_xor_sync(0xffffffffu, sumB, 2);
        lA = lA * alA + sumA;
        lB = lB * alB + sumB;
#pragma unroll
        for (int nt = 0; nt < 8; ++nt) {
            o[nt][0] *= alA; o[nt][1] *= alA;
            o[nt][2] *= alB; o[nt][3] *= alB;
        }

        cpa_wait_all();
        __syncthreads();              // V(c) ready; S-mma done with KT
        if (c + 1 < 32) { loadKT(c + 1); cpa_commit(); }

        // ---- O += P @ V; P A-fragments straight from registers ----
#pragma unroll
        for (int ks = 0; ks < 4; ++ks) {
            const uint32_t a0h = ph[4 * ks],     a1h = ph[4 * ks + 1];
            const uint32_t a2h = ph[4 * ks + 2], a3h = ph[4 * ks + 3];
            const uint32_t a0l = pl[4 * ks],     a1l = pl[4 * ks + 1];
            const uint32_t a2l = pl[4 * ks + 2], a3l = pl[4 * ks + 3];
#pragma unroll
            for (int np = 0; np < 4; ++np) {
                const int ntA = np * 2, ntB = ntA + 1;
                uint4 bh4 = V4h[(ks * 4 + np) * 32 + lane];
                uint4 bl4 = V4l[(ks * 4 + np) * 32 + lane];
                mma16816(o[ntA], a0h, a1h, a2h, a3h, bh4.x, bh4.y);
                mma16816(o[ntB], a0h, a1h, a2h, a3h, bh4.z, bh4.w);
                mma16816(o[ntA], a0h, a1h, a2h, a3h, bl4.x, bl4.y);
                mma16816(o[ntB], a0h, a1h, a2h, a3h, bl4.z, bl4.w);
                mma16816(o[ntA], a0l, a1l, a2l, a3l, bh4.x, bh4.y);
                mma16816(o[ntB], a0l, a1l, a2l, a3l, bh4.z, bh4.w);
            }
        }
    }

    // normalize + store as pairs (input layout for O-projection gemm)
    float invA = 1.f / lA;
    float invB = 1.f / lB;
    size_t r0 = (size_t)(rowbase + q0 + warp * 16 + g) * KP + h * 32;
    size_t r1 = r0 + 8 * KP;
#pragma unroll
    for (int nt = 0; nt < 8; ++nt) {
        int dpi = nt * 4 + tig;
        uint32_t hh, ll;
        split2(o[nt][0] * invA, o[nt][1] * invA, hh, ll);
        g_Oh[r0 + dpi] = hh; g_Ol[r0 + dpi] = ll;
        split2(o[nt][2] * invB, o[nt][3] * invB, hh, ll);
        g_Oh[r1 + dpi] = hh; g_Ol[r1 + dpi] = ll;
    }
}

// ---------------------------------------------------------------------------
extern "C" void kernel_launch(void* const* d_in, const int* in_sizes, int n_in,
                              void* d_out, int out_size)
{
    (void)in_sizes; (void)n_in; (void)out_size;

    const float* mod1 = (const float*)d_in[0];
    const float* mod2 = (const float*)d_in[1];
    const float* Wq  = (const float*)d_in[2];  const float* bq  = (const float*)d_in[3];
    const float* Wk  = (const float*)d_in[4];  const float* bk  = (const float*)d_in[5];
    const float* Wv  = (const float*)d_in[6];  const float* bv  = (const float*)d_in[7];
    const float* Wo  = (const float*)d_in[8];  const float* bo  = (const float*)d_in[9];
    const float* Ws  = (const float*)d_in[10]; const float* bs  = (const float*)d_in[11];
    const float* Wsh = (const float*)d_in[12]; const float* bsh = (const float*)d_in[13];
    float* out = (float*)d_out;

    const int GEMM_SMEM = (2 * 64 * GLDA * 2 + 2 * 16 * GLDB * 2) * 4;   // 55296 B
    const int ATTN_SMEM = 4 * 2048 * 4;                                  // 32768 B
    cudaFuncSetAttribute(gemm_qkvsh, cudaFuncAttributeMaxDynamicSharedMemorySize, GEMM_SMEM);
    cudaFuncSetAttribute(gemm_oproj, cudaFuncAttributeMaxDynamicSharedMemorySize, GEMM_SMEM);
    cudaFuncSetAttribute(attn_pairs, cudaFuncAttributeMaxDynamicSharedMemorySize, ATTN_SMEM);

    // 1) conversions (3 launches)
    conv_rows_all<<<dim3(MTOT * KP / 4 / 256, 2), 256>>>(mod1, mod2);
    conv_cols_all<<<dim3(128, 6), 256>>>(Wq, Wk, Wv, Ws, Wsh, Wo);
    bias_pack<<<8, 256>>>(bk, bv, bs, bsh);

    // 2) merged Q + K|V|S|H projection (one 2560-block launch)
    gemm_qkvsh<<<dim3(20, MTOT / 64), 128, GEMM_SMEM>>>(bq);

    // 3) apply scale/shift + pack fragment-order K/V blobs (smem-staged)
    kvss_pack<<<dim3(HH, 128), 256>>>();

    // 4) attention (64-q tiles, 128 threads, register-P, vector B loads)
    attn_pairs<<<dim3(SS / 64, HH, BB), 128, ATTN_SMEM>>>();

    // 5) output projection
    gemm_oproj<<<dim3(DD / 128, MTOT / 64), 128, GEMM_SMEM>>>(bo, out);
}